// round 3
// baseline (speedup 1.0000x reference)
#include <cuda_runtime.h>
#include <cstdint>

#define D 128
#define TM 64
#define KPAD 264                 // 256 + 8 pad (keeps float4 alignment, kills conflicts)
#define HPAD 132                 // 128 + 4 pad for hidden tile
#define SIN_F (TM * KPAD)        // floats for input tile region (also reused for hidden)
#define SW1_F (256 * 128)
#define SMEM_BYTES ((SIN_F + SW1_F) * 4)

// Scratch for the scatter-add aggregate (25.6 MB). Static __device__ array per rules.
__device__ float g_agg[50000 * D];

// ---------------------------------------------------------------------------
__global__ void zero_agg_kernel(int n4) {
    int i = blockIdx.x * blockDim.x + threadIdx.x;
    if (i < n4) {
        float4 z = {0.f, 0.f, 0.f, 0.f};
        reinterpret_cast<float4*>(g_agg)[i] = z;
    }
}

// One thread per (edge, 4-column group): coalesced 16B load, 4 float atomics into
// g_agg (L2-resident: 25.6MB < 126MB L2, so these are L2 atomics, no DRAM RMW).
__global__ void scatter_kernel(const float* __restrict__ edge_attr,
                               const int* __restrict__ recv, int E) {
    long long i = (long long)blockIdx.x * blockDim.x + threadIdx.x;
    if (i >= (long long)E * (D / 4)) return;
    int e  = (int)(i >> 5);          // D/4 = 32 groups per edge
    int c4 = ((int)i & 31) << 2;
    float4 v = reinterpret_cast<const float4*>(edge_attr + (size_t)e * D)[c4 >> 2];
    int r = recv[e];
    float* dst = g_agg + (size_t)r * D + c4;
    atomicAdd(dst + 0, v.x);
    atomicAdd(dst + 1, v.y);
    atomicAdd(dst + 2, v.z);
    atomicAdd(dst + 3, v.w);
}

// ---------------------------------------------------------------------------
// Fused MLP: per-CTA tile of TM=64 nodes.
//   smem: sIn [64][264]  (concat x|agg along k; reused as sH [64][132] for GEMM2)
//         sW1 [256][128]
//   thread (256/block): cols cg = (tid%32)*4, nodes ng = (tid/32)*8  -> 8x4 acc tile
//   GEMM1: k=0..255 step 4; a = float4 along k (warp-broadcast LDS.128),
//          b = 4 rows of W1 (conflict-free LDS.128). 128 FMA / 12 LDS per step.
//   GEMM2: same shape, k=0..127, W2 via LDG (64KB, L1-resident).
__global__ __launch_bounds__(256, 1)
void mlp_kernel(const float* __restrict__ x,
                const float* __restrict__ W1, const float* __restrict__ b1,
                const float* __restrict__ W2, const float* __restrict__ b2,
                float* __restrict__ out, int nNodes) {
    extern __shared__ float smem[];
    float* sIn = smem;               // TM x KPAD  (later reused as sH: TM x HPAD)
    float* sW1 = smem + SIN_F;       // 256 x 128

    const int tid = threadIdx.x;
    const int cg = (tid & 31) * 4;   // output column group
    const int ng = (tid >> 5) * 8;   // node group within tile

    // Load W1 into smem (coalesced float4)
    {
        const float4* src = reinterpret_cast<const float4*>(W1);
        float4* dst = reinterpret_cast<float4*>(sW1);
        #pragma unroll
        for (int i = tid; i < SW1_F / 4; i += 256) dst[i] = src[i];
    }

    const float4 vb1 = *reinterpret_cast<const float4*>(b1 + cg);
    const float4 vb2 = *reinterpret_cast<const float4*>(b2 + cg);

    const int base = blockIdx.x * TM;

    // ---- Load input tile: sIn[n][k] = concat(x[node], agg[node]) ----
    for (int i = tid; i < TM * 64; i += 256) {
        int n  = i >> 6;
        int k4 = i & 63;
        int node = base + n;
        float4 v = {0.f, 0.f, 0.f, 0.f};
        if (node < nNodes) {
            if (k4 < 32)
                v = reinterpret_cast<const float4*>(x + (size_t)node * D)[k4];
            else
                v = reinterpret_cast<const float4*>(g_agg + (size_t)node * D)[k4 - 32];
        }
        *reinterpret_cast<float4*>(sIn + n * KPAD + k4 * 4) = v;
    }
    __syncthreads();

    // ---- GEMM1: hidden = relu(In @ W1 + b1) ----
    float acc[8][4];
    #pragma unroll
    for (int n = 0; n < 8; n++)
        #pragma unroll
        for (int c = 0; c < 4; c++) acc[n][c] = 0.f;

    #pragma unroll 4
    for (int k = 0; k < 256; k += 4) {
        float4 w0 = *reinterpret_cast<const float4*>(sW1 + (k + 0) * 128 + cg);
        float4 w1 = *reinterpret_cast<const float4*>(sW1 + (k + 1) * 128 + cg);
        float4 w2 = *reinterpret_cast<const float4*>(sW1 + (k + 2) * 128 + cg);
        float4 w3 = *reinterpret_cast<const float4*>(sW1 + (k + 3) * 128 + cg);
        #pragma unroll
        for (int n = 0; n < 8; n++) {
            float4 a = *reinterpret_cast<const float4*>(sIn + (ng + n) * KPAD + k);
            acc[n][0] += a.x * w0.x + a.y * w1.x + a.z * w2.x + a.w * w3.x;
            acc[n][1] += a.x * w0.y + a.y * w1.y + a.z * w2.y + a.w * w3.y;
            acc[n][2] += a.x * w0.z + a.y * w1.z + a.z * w2.z + a.w * w3.z;
            acc[n][3] += a.x * w0.w + a.y * w1.w + a.z * w2.w + a.w * w3.w;
        }
    }

    // bias + relu
    #pragma unroll
    for (int n = 0; n < 8; n++) {
        acc[n][0] = fmaxf(acc[n][0] + vb1.x, 0.f);
        acc[n][1] = fmaxf(acc[n][1] + vb1.y, 0.f);
        acc[n][2] = fmaxf(acc[n][2] + vb1.z, 0.f);
        acc[n][3] = fmaxf(acc[n][3] + vb1.w, 0.f);
    }

    __syncthreads();  // everyone done reading sIn
    // write hidden tile into (reused) sIn region as sH[n][c], pad HPAD
    float* sH = sIn;
    #pragma unroll
    for (int n = 0; n < 8; n++) {
        float4 h = make_float4(acc[n][0], acc[n][1], acc[n][2], acc[n][3]);
        *reinterpret_cast<float4*>(sH + (ng + n) * HPAD + cg) = h;
    }
    __syncthreads();

    // ---- GEMM2: out = H @ W2 + b2 (W2 via LDG, L1-resident) ----
    #pragma unroll
    for (int n = 0; n < 8; n++)
        #pragma unroll
        for (int c = 0; c < 4; c++) acc[n][c] = 0.f;

    #pragma unroll 4
    for (int k = 0; k < 128; k += 4) {
        float4 w0 = *reinterpret_cast<const float4*>(W2 + (size_t)(k + 0) * 128 + cg);
        float4 w1 = *reinterpret_cast<const float4*>(W2 + (size_t)(k + 1) * 128 + cg);
        float4 w2 = *reinterpret_cast<const float4*>(W2 + (size_t)(k + 2) * 128 + cg);
        float4 w3 = *reinterpret_cast<const float4*>(W2 + (size_t)(k + 3) * 128 + cg);
        #pragma unroll
        for (int n = 0; n < 8; n++) {
            float4 a = *reinterpret_cast<const float4*>(sH + (ng + n) * HPAD + k);
            acc[n][0] += a.x * w0.x + a.y * w1.x + a.z * w2.x + a.w * w3.x;
            acc[n][1] += a.x * w0.y + a.y * w1.y + a.z * w2.y + a.w * w3.y;
            acc[n][2] += a.x * w0.z + a.y * w1.z + a.z * w2.z + a.w * w3.z;
            acc[n][3] += a.x * w0.w + a.y * w1.w + a.z * w2.w + a.w * w3.w;
        }
    }

    // bias + store
    #pragma unroll
    for (int n = 0; n < 8; n++) {
        int node = base + ng + n;
        if (node < nNodes) {
            float4 o = make_float4(acc[n][0] + vb2.x, acc[n][1] + vb2.y,
                                   acc[n][2] + vb2.z, acc[n][3] + vb2.w);
            *reinterpret_cast<float4*>(out + (size_t)node * D + cg) = o;
        }
    }
}

// ---------------------------------------------------------------------------
extern "C" void kernel_launch(void* const* d_in, const int* in_sizes, int n_in,
                              void* d_out, int out_size) {
    const float* x         = (const float*)d_in[0];
    const float* edge_attr = (const float*)d_in[1];
    const int*   recv      = (const int*)d_in[2];
    const float* W1        = (const float*)d_in[3];
    const float* b1        = (const float*)d_in[4];
    const float* W2        = (const float*)d_in[5];
    const float* b2        = (const float*)d_in[6];
    float* out = (float*)d_out;

    int nNodes = in_sizes[0] / D;
    int E      = in_sizes[2];

    // Opt-in to large dynamic smem (host-side attribute, not a stream op)
    cudaFuncSetAttribute(mlp_kernel, cudaFuncAttributeMaxDynamicSharedMemorySize,
                         SMEM_BYTES);

    // 1) zero aggregate
    int n4 = nNodes * D / 4;
    zero_agg_kernel<<<(n4 + 255) / 256, 256>>>(n4);

    // 2) scatter-add edge features
    long long threads = (long long)E * (D / 4);
    int sblocks = (int)((threads + 255) / 256);
    scatter_kernel<<<sblocks, 256>>>(edge_attr, recv, E);

    // 3) fused MLP
    int tiles = (nNodes + TM - 1) / TM;
    mlp_kernel<<<tiles, 256, SMEM_BYTES>>>(x, W1, b1, W2, b2, out, nNodes);
}

// round 4
// speedup vs baseline: 1.4438x; 1.4438x over previous
#include <cuda_runtime.h>
#include <cstdint>

#define D 128
#define TM 64
#define KPAD 264                 // 256 + 8 pad (keeps float4 alignment, kills conflicts)
#define HPAD 132                 // 128 + 4 pad for hidden tile
#define SIN_F (TM * KPAD)        // floats for input tile region (also reused for hidden)
#define SW1_F (256 * 128)
#define SMEM_BYTES ((SIN_F + SW1_F) * 4)

// Scratch for the scatter-add aggregate (25.6 MB). Static __device__ array per rules.
__device__ float g_agg[50000 * D];

// ---------------------------------------------------------------------------
__global__ void zero_agg_kernel(int n4) {
    int i = blockIdx.x * blockDim.x + threadIdx.x;
    if (i < n4) {
        float4 z = {0.f, 0.f, 0.f, 0.f};
        reinterpret_cast<float4*>(g_agg)[i] = z;
    }
}

// One thread per (edge, 4-column group): coalesced 16B load, ONE vectorized
// red.global.add.v4.f32 (sm_90+) instead of 4 scalar atomics. g_agg is
// L2-resident (25.6MB < 126MB), so these are L2 atomics, no DRAM RMW.
__global__ void scatter_kernel(const float* __restrict__ edge_attr,
                               const int* __restrict__ recv, int E) {
    long long i = (long long)blockIdx.x * blockDim.x + threadIdx.x;
    if (i >= (long long)E * (D / 4)) return;
    int e  = (int)(i >> 5);          // D/4 = 32 groups per edge
    int c4 = ((int)i & 31) << 2;
    float4 v = reinterpret_cast<const float4*>(edge_attr + (size_t)e * D)[c4 >> 2];
    int r = recv[e];
    float* dst = g_agg + (size_t)r * D + c4;
    asm volatile("red.global.add.v4.f32 [%0], {%1, %2, %3, %4};"
                 :: "l"(dst), "f"(v.x), "f"(v.y), "f"(v.z), "f"(v.w)
                 : "memory");
}

// ---------------------------------------------------------------------------
// Fused MLP: per-CTA tile of TM=64 nodes.
//   smem: sIn [64][264]  (concat x|agg along k; reused as sH [64][132] for GEMM2)
//         sW1 [256][128]
//   thread (256/block): cols cg = (tid%32)*4, nodes ng = (tid/32)*8  -> 8x4 acc tile
//   GEMM1: k=0..255 step 4; a = float4 along k (warp-broadcast LDS.128),
//          b = 4 rows of W1 (conflict-free LDS.128). 128 FMA / 12 LDS per step.
//   GEMM2: same shape, k=0..127, W2 via LDG (64KB, L1-resident).
__global__ __launch_bounds__(256, 1)
void mlp_kernel(const float* __restrict__ x,
                const float* __restrict__ W1, const float* __restrict__ b1,
                const float* __restrict__ W2, const float* __restrict__ b2,
                float* __restrict__ out, int nNodes) {
    extern __shared__ float smem[];
    float* sIn = smem;               // TM x KPAD  (later reused as sH: TM x HPAD)
    float* sW1 = smem + SIN_F;       // 256 x 128

    const int tid = threadIdx.x;
    const int cg = (tid & 31) * 4;   // output column group
    const int ng = (tid >> 5) * 8;   // node group within tile

    // Load W1 into smem (coalesced float4)
    {
        const float4* src = reinterpret_cast<const float4*>(W1);
        float4* dst = reinterpret_cast<float4*>(sW1);
        #pragma unroll
        for (int i = tid; i < SW1_F / 4; i += 256) dst[i] = src[i];
    }

    const float4 vb1 = *reinterpret_cast<const float4*>(b1 + cg);
    const float4 vb2 = *reinterpret_cast<const float4*>(b2 + cg);

    const int base = blockIdx.x * TM;

    // ---- Load input tile: sIn[n][k] = concat(x[node], agg[node]) ----
    for (int i = tid; i < TM * 64; i += 256) {
        int n  = i >> 6;
        int k4 = i & 63;
        int node = base + n;
        float4 v = {0.f, 0.f, 0.f, 0.f};
        if (node < nNodes) {
            if (k4 < 32)
                v = reinterpret_cast<const float4*>(x + (size_t)node * D)[k4];
            else
                v = reinterpret_cast<const float4*>(g_agg + (size_t)node * D)[k4 - 32];
        }
        *reinterpret_cast<float4*>(sIn + n * KPAD + k4 * 4) = v;
    }
    __syncthreads();

    // ---- GEMM1: hidden = relu(In @ W1 + b1) ----
    float acc[8][4];
    #pragma unroll
    for (int n = 0; n < 8; n++)
        #pragma unroll
        for (int c = 0; c < 4; c++) acc[n][c] = 0.f;

    #pragma unroll 4
    for (int k = 0; k < 256; k += 4) {
        float4 w0 = *reinterpret_cast<const float4*>(sW1 + (k + 0) * 128 + cg);
        float4 w1 = *reinterpret_cast<const float4*>(sW1 + (k + 1) * 128 + cg);
        float4 w2 = *reinterpret_cast<const float4*>(sW1 + (k + 2) * 128 + cg);
        float4 w3 = *reinterpret_cast<const float4*>(sW1 + (k + 3) * 128 + cg);
        #pragma unroll
        for (int n = 0; n < 8; n++) {
            float4 a = *reinterpret_cast<const float4*>(sIn + (ng + n) * KPAD + k);
            acc[n][0] += a.x * w0.x + a.y * w1.x + a.z * w2.x + a.w * w3.x;
            acc[n][1] += a.x * w0.y + a.y * w1.y + a.z * w2.y + a.w * w3.y;
            acc[n][2] += a.x * w0.z + a.y * w1.z + a.z * w2.z + a.w * w3.z;
            acc[n][3] += a.x * w0.w + a.y * w1.w + a.z * w2.w + a.w * w3.w;
        }
    }

    // bias + relu
    #pragma unroll
    for (int n = 0; n < 8; n++) {
        acc[n][0] = fmaxf(acc[n][0] + vb1.x, 0.f);
        acc[n][1] = fmaxf(acc[n][1] + vb1.y, 0.f);
        acc[n][2] = fmaxf(acc[n][2] + vb1.z, 0.f);
        acc[n][3] = fmaxf(acc[n][3] + vb1.w, 0.f);
    }

    __syncthreads();  // everyone done reading sIn
    // write hidden tile into (reused) sIn region as sH[n][c], pad HPAD
    float* sH = sIn;
    #pragma unroll
    for (int n = 0; n < 8; n++) {
        float4 h = make_float4(acc[n][0], acc[n][1], acc[n][2], acc[n][3]);
        *reinterpret_cast<float4*>(sH + (ng + n) * HPAD + cg) = h;
    }
    __syncthreads();

    // ---- GEMM2: out = H @ W2 + b2 (W2 via LDG, L1-resident) ----
    #pragma unroll
    for (int n = 0; n < 8; n++)
        #pragma unroll
        for (int c = 0; c < 4; c++) acc[n][c] = 0.f;

    #pragma unroll 4
    for (int k = 0; k < 128; k += 4) {
        float4 w0 = *reinterpret_cast<const float4*>(W2 + (size_t)(k + 0) * 128 + cg);
        float4 w1 = *reinterpret_cast<const float4*>(W2 + (size_t)(k + 1) * 128 + cg);
        float4 w2 = *reinterpret_cast<const float4*>(W2 + (size_t)(k + 2) * 128 + cg);
        float4 w3 = *reinterpret_cast<const float4*>(W2 + (size_t)(k + 3) * 128 + cg);
        #pragma unroll
        for (int n = 0; n < 8; n++) {
            float4 a = *reinterpret_cast<const float4*>(sH + (ng + n) * HPAD + k);
            acc[n][0] += a.x * w0.x + a.y * w1.x + a.z * w2.x + a.w * w3.x;
            acc[n][1] += a.x * w0.y + a.y * w1.y + a.z * w2.y + a.w * w3.y;
            acc[n][2] += a.x * w0.z + a.y * w1.z + a.z * w2.z + a.w * w3.z;
            acc[n][3] += a.x * w0.w + a.y * w1.w + a.z * w2.w + a.w * w3.w;
        }
    }

    // bias + store
    #pragma unroll
    for (int n = 0; n < 8; n++) {
        int node = base + ng + n;
        if (node < nNodes) {
            float4 o = make_float4(acc[n][0] + vb2.x, acc[n][1] + vb2.y,
                                   acc[n][2] + vb2.z, acc[n][3] + vb2.w);
            *reinterpret_cast<float4*>(out + (size_t)node * D + cg) = o;
        }
    }
}

// ---------------------------------------------------------------------------
extern "C" void kernel_launch(void* const* d_in, const int* in_sizes, int n_in,
                              void* d_out, int out_size) {
    const float* x         = (const float*)d_in[0];
    const float* edge_attr = (const float*)d_in[1];
    const int*   recv      = (const int*)d_in[2];
    const float* W1        = (const float*)d_in[3];
    const float* b1        = (const float*)d_in[4];
    const float* W2        = (const float*)d_in[5];
    const float* b2        = (const float*)d_in[6];
    float* out = (float*)d_out;

    int nNodes = in_sizes[0] / D;
    int E      = in_sizes[2];

    // Opt-in to large dynamic smem (host-side attribute, not a stream op)
    cudaFuncSetAttribute(mlp_kernel, cudaFuncAttributeMaxDynamicSharedMemorySize,
                         SMEM_BYTES);

    // 1) zero aggregate
    int n4 = nNodes * D / 4;
    zero_agg_kernel<<<(n4 + 255) / 256, 256>>>(n4);

    // 2) scatter-add edge features (vectorized v4 reductions)
    long long threads = (long long)E * (D / 4);
    int sblocks = (int)((threads + 255) / 256);
    scatter_kernel<<<sblocks, 256>>>(edge_attr, recv, E);

    // 3) fused MLP
    int tiles = (nNodes + TM - 1) / TM;
    mlp_kernel<<<tiles, 256, SMEM_BYTES>>>(x, W1, b1, W2, b2, out, nNodes);
}

// round 5
// speedup vs baseline: 1.5545x; 1.0767x over previous
#include <cuda_runtime.h>
#include <cstdint>

#define D 128
#define TM 64
#define THREADS 256
#define AROW 132                        // floats per k-row of dup'd activation tile (128 dup + 4 pad)
#define SA_F (128 * AROW)               // one k-half, duplicated: 16896 floats
#define SW_F (256 * 128)                // full W1
#define SMEM_BYTES ((SA_F + SW_F) * 4)  // 198,656 B

// Scratch for the scatter-add aggregate (25.6 MB). Static __device__ array per rules.
__device__ float g_agg[50000 * D];

// ---------------------------------------------------------------------------
__global__ void zero_agg_kernel(int n4) {
    int i = blockIdx.x * blockDim.x + threadIdx.x;
    if (i < n4) {
        float4 z = {0.f, 0.f, 0.f, 0.f};
        reinterpret_cast<float4*>(g_agg)[i] = z;
    }
}

// One thread per (edge, 4-column group): coalesced 16B load, ONE vectorized
// red.global.add.v4.f32. g_agg is L2-resident (25.6MB < 126MB).
__global__ void scatter_kernel(const float* __restrict__ edge_attr,
                               const int* __restrict__ recv, int E) {
    long long i = (long long)blockIdx.x * blockDim.x + threadIdx.x;
    if (i >= (long long)E * (D / 4)) return;
    int e  = (int)(i >> 5);
    int c4 = ((int)i & 31) << 2;
    float4 v = reinterpret_cast<const float4*>(edge_attr + (size_t)e * D)[c4 >> 2];
    int r = recv[e];
    float* dst = g_agg + (size_t)r * D + c4;
    asm volatile("red.global.add.v4.f32 [%0], {%1, %2, %3, %4};"
                 :: "l"(dst), "f"(v.x), "f"(v.y), "f"(v.z), "f"(v.w)
                 : "memory");
}

// ---------------------------------------------------------------------------
// Packed-f32x2 helpers (sm_100+). Exact fp32 math, 2 FMAs per instruction.
__device__ __forceinline__ void fma2(unsigned long long& d,
                                     unsigned long long a, unsigned long long b) {
    asm("fma.rn.f32x2 %0, %1, %2, %0;" : "+l"(d) : "l"(a), "l"(b));
}
__device__ __forceinline__ float2 unpk(unsigned long long p) {
    float2 r;
    asm("mov.b64 {%0, %1}, %2;" : "=f"(r.x), "=f"(r.y) : "l"(p));
    return r;
}
__device__ __forceinline__ unsigned long long pk(float lo, float hi) {
    unsigned long long p;
    asm("mov.b64 %0, {%1, %2};" : "=l"(p) : "f"(lo), "f"(hi));
    return p;
}

// ---------------------------------------------------------------------------
// Fused MLP, packed-f32x2 formulation.
//   Warp w owns output columns [16w, 16w+16). Lane l owns tile-nodes 2l, 2l+1.
//   acc[node-slot 0..1][cpair 0..7] : ull packed over adjacent output columns.
//   sA[k][AROW]: activation value of node n at row k stored DUPLICATED at
//                word offset 2n -> one LDS.128 at 4*lane yields both nodes'
//                {a,a} pairs, conflict-free. Two k-phases (x half, agg half).
//   sW: plain W1 (256x128, resident across both phases); reused for W2.
//   Inner loop per k: 1 LDS.128 (a) + 4 broadcast LDS.128 (w) + 16 FFMA2.
__global__ __launch_bounds__(THREADS, 1)
void mlp_kernel(const float* __restrict__ x,
                const float* __restrict__ W1, const float* __restrict__ b1,
                const float* __restrict__ W2, const float* __restrict__ b2,
                float* __restrict__ out, int nNodes) {
    extern __shared__ float smem[];
    float* sA = smem;            // [128][AROW] dup'd activations (reused for hidden)
    float* sW = smem + SA_F;     // weights

    const int tid  = threadIdx.x;
    const int lane = tid & 31;
    const int warp = tid >> 5;
    const int wc   = warp * 16;            // warp's output-column base
    const int base = blockIdx.x * TM;
    const int n0   = 2 * lane;             // thread's two tile-local nodes

    // ---- load full W1 (256x128) into sW, coalesced float4 ----
    {
        const float4* src = reinterpret_cast<const float4*>(W1);
        float4* dst = reinterpret_cast<float4*>(sW);
        #pragma unroll
        for (int i = tid; i < SW_F / 4; i += THREADS) dst[i] = src[i];
    }

    unsigned long long acc[2][8];
    #pragma unroll
    for (int a = 0; a < 2; a++)
        #pragma unroll
        for (int c = 0; c < 8; c++) acc[a][c] = 0ull;

    // ---- GEMM1 in two k-phases: K 0..127 = x, K 128..255 = g_agg ----
    for (int phase = 0; phase < 2; phase++) {
        const float* src = (phase == 0) ? x : g_agg;
        if (phase == 1) __syncthreads();   // all warps done reading previous sA

        // fill sA: node n's value at k goes (duplicated) to sA[k*AROW + 2n]
        for (int i = tid; i < TM * 32; i += THREADS) {
            int n  = i & 63;               // lanes differ in n -> contiguous STS.64
            int k4 = i >> 6;
            int node = base + n;
            float4 v = {0.f, 0.f, 0.f, 0.f};
            if (node < nNodes)
                v = reinterpret_cast<const float4*>(src + (size_t)node * D)[k4];
            *(unsigned long long*)(sA + (4 * k4 + 0) * AROW + 2 * n) = pk(v.x, v.x);
            *(unsigned long long*)(sA + (4 * k4 + 1) * AROW + 2 * n) = pk(v.y, v.y);
            *(unsigned long long*)(sA + (4 * k4 + 2) * AROW + 2 * n) = pk(v.z, v.z);
            *(unsigned long long*)(sA + (4 * k4 + 3) * AROW + 2 * n) = pk(v.w, v.w);
        }
        __syncthreads();

        const float* wbase = sW + phase * 128 * 128 + wc;
        #pragma unroll 8
        for (int k = 0; k < 128; k++) {
            ulonglong2 av = *reinterpret_cast<const ulonglong2*>(sA + k * AROW + 4 * lane);
            const ulonglong2* wp = reinterpret_cast<const ulonglong2*>(wbase + k * 128);
            ulonglong2 wA = wp[0], wB = wp[1], wC = wp[2], wE = wp[3];
            fma2(acc[0][0], av.x, wA.x); fma2(acc[0][1], av.x, wA.y);
            fma2(acc[0][2], av.x, wB.x); fma2(acc[0][3], av.x, wB.y);
            fma2(acc[0][4], av.x, wC.x); fma2(acc[0][5], av.x, wC.y);
            fma2(acc[0][6], av.x, wE.x); fma2(acc[0][7], av.x, wE.y);
            fma2(acc[1][0], av.y, wA.x); fma2(acc[1][1], av.y, wA.y);
            fma2(acc[1][2], av.y, wB.x); fma2(acc[1][3], av.y, wB.y);
            fma2(acc[1][4], av.y, wC.x); fma2(acc[1][5], av.y, wC.y);
            fma2(acc[1][6], av.y, wE.x); fma2(acc[1][7], av.y, wE.y);
        }
    }

    __syncthreads();   // GEMM1 reads of sA and sW complete everywhere

    // ---- bias + relu; write hidden (duplicated) back into sA; load W2 ----
    #pragma unroll
    for (int cp = 0; cp < 8; cp++) {
        int c0 = wc + 2 * cp, c1 = c0 + 1;
        float2 h0 = unpk(acc[0][cp]);      // node n0 : cols (c0, c1)
        float2 h1 = unpk(acc[1][cp]);      // node n0+1
        float bc0 = b1[c0], bc1 = b1[c1];
        float v00 = fmaxf(h0.x + bc0, 0.f), v01 = fmaxf(h0.y + bc1, 0.f);
        float v10 = fmaxf(h1.x + bc0, 0.f), v11 = fmaxf(h1.y + bc1, 0.f);
        *(unsigned long long*)(sA + c0 * AROW + 4 * lane)     = pk(v00, v00);
        *(unsigned long long*)(sA + c0 * AROW + 4 * lane + 2) = pk(v10, v10);
        *(unsigned long long*)(sA + c1 * AROW + 4 * lane)     = pk(v01, v01);
        *(unsigned long long*)(sA + c1 * AROW + 4 * lane + 2) = pk(v11, v11);
    }
    {
        const float4* src = reinterpret_cast<const float4*>(W2);
        float4* dst = reinterpret_cast<float4*>(sW);
        #pragma unroll
        for (int i = tid; i < (128 * 128) / 4; i += THREADS) dst[i] = src[i];
    }
    __syncthreads();

    // ---- GEMM2: out = H @ W2 + b2 ----
    #pragma unroll
    for (int a = 0; a < 2; a++)
        #pragma unroll
        for (int c = 0; c < 8; c++) acc[a][c] = 0ull;

    #pragma unroll 8
    for (int k = 0; k < 128; k++) {
        ulonglong2 av = *reinterpret_cast<const ulonglong2*>(sA + k * AROW + 4 * lane);
        const ulonglong2* wp = reinterpret_cast<const ulonglong2*>(sW + k * 128 + wc);
        ulonglong2 wA = wp[0], wB = wp[1], wC = wp[2], wE = wp[3];
        fma2(acc[0][0], av.x, wA.x); fma2(acc[0][1], av.x, wA.y);
        fma2(acc[0][2], av.x, wB.x); fma2(acc[0][3], av.x, wB.y);
        fma2(acc[0][4], av.x, wC.x); fma2(acc[0][5], av.x, wC.y);
        fma2(acc[0][6], av.x, wE.x); fma2(acc[0][7], av.x, wE.y);
        fma2(acc[1][0], av.y, wA.x); fma2(acc[1][1], av.y, wA.y);
        fma2(acc[1][2], av.y, wB.x); fma2(acc[1][3], av.y, wB.y);
        fma2(acc[1][4], av.y, wC.x); fma2(acc[1][5], av.y, wC.y);
        fma2(acc[1][6], av.y, wE.x); fma2(acc[1][7], av.y, wE.y);
    }

    // ---- bias + store ----
    float o[2][16];
    #pragma unroll
    for (int cp = 0; cp < 8; cp++) {
        int c0 = wc + 2 * cp, c1 = c0 + 1;
        float2 p0 = unpk(acc[0][cp]);
        float2 p1 = unpk(acc[1][cp]);
        float bc0 = b2[c0], bc1 = b2[c1];
        o[0][2 * cp]     = p0.x + bc0;
        o[0][2 * cp + 1] = p0.y + bc1;
        o[1][2 * cp]     = p1.x + bc0;
        o[1][2 * cp + 1] = p1.y + bc1;
    }
    #pragma unroll
    for (int q = 0; q < 2; q++) {
        int node = base + n0 + q;
        if (node < nNodes) {
            float* dst = out + (size_t)node * D + wc;
            #pragma unroll
            for (int t = 0; t < 4; t++) {
                float4 v = make_float4(o[q][4 * t], o[q][4 * t + 1],
                                       o[q][4 * t + 2], o[q][4 * t + 3]);
                *reinterpret_cast<float4*>(dst + 4 * t) = v;
            }
        }
    }
}

// ---------------------------------------------------------------------------
extern "C" void kernel_launch(void* const* d_in, const int* in_sizes, int n_in,
                              void* d_out, int out_size) {
    const float* x         = (const float*)d_in[0];
    const float* edge_attr = (const float*)d_in[1];
    const int*   recv      = (const int*)d_in[2];
    const float* W1        = (const float*)d_in[3];
    const float* b1        = (const float*)d_in[4];
    const float* W2        = (const float*)d_in[5];
    const float* b2        = (const float*)d_in[6];
    float* out = (float*)d_out;

    int nNodes = in_sizes[0] / D;
    int E      = in_sizes[2];

    cudaFuncSetAttribute(mlp_kernel, cudaFuncAttributeMaxDynamicSharedMemorySize,
                         SMEM_BYTES);

    // 1) zero aggregate
    int n4 = nNodes * D / 4;
    zero_agg_kernel<<<(n4 + 255) / 256, 256>>>(n4);

    // 2) scatter-add edge features (vectorized v4 reductions)
    long long threads = (long long)E * (D / 4);
    int sblocks = (int)((threads + 255) / 256);
    scatter_kernel<<<sblocks, 256>>>(edge_attr, recv, E);

    // 3) fused MLP (packed f32x2)
    int tiles = (nNodes + TM - 1) / TM;
    mlp_kernel<<<tiles, THREADS, SMEM_BYTES>>>(x, W1, b1, W2, b2, out, nNodes);
}